// round 2
// baseline (speedup 1.0000x reference)
#include <cuda_runtime.h>
#include <cstdint>

// Per-row stream compaction:
//   x3: [B*C, L] f32, L=16384. Drop entries exactly equal to 10.1f, keep
//   order, emit first KEEP=12288 survivors per row. Setup guarantees exactly
//   L-KEEP fillers per row, so output is fully written.
// x1, x2, keep_len are unused by the reference computation (shapes fixed).

#define FILLER 10.1f

constexpr int L_DIM   = 16384;
constexpr int KEEP    = 12288;
constexpr int THREADS = 1024;
constexpr int PER_T   = L_DIM / THREADS;   // 16 elements per thread
constexpr int VEC     = PER_T / 4;         // 4 float4 loads per thread

__global__ __launch_bounds__(THREADS, 2)
void compact_rows_kernel(const float* __restrict__ x3,
                         float* __restrict__ out,
                         int n_rows)
{
    const int row = blockIdx.x;
    if (row >= n_rows) return;

    const float* __restrict__ in = x3 + (size_t)row * L_DIM;
    float* __restrict__ o        = out + (size_t)row * KEEP;

    const int tid  = threadIdx.x;
    const int lane = tid & 31;
    const int wid  = tid >> 5;

    // Each thread owns a contiguous run of 16 elements (order preservation).
    float v[PER_T];
    const float4* __restrict__ in4 =
        reinterpret_cast<const float4*>(in + tid * PER_T);
#pragma unroll
    for (int j = 0; j < VEC; ++j) {
        float4 t = in4[j];
        v[4 * j + 0] = t.x;
        v[4 * j + 1] = t.y;
        v[4 * j + 2] = t.z;
        v[4 * j + 3] = t.w;
    }

    // Survivor count for this thread.
    int c = 0;
#pragma unroll
    for (int i = 0; i < PER_T; ++i) c += (v[i] != FILLER) ? 1 : 0;

    // Warp-level inclusive scan of counts.
    int inc = c;
#pragma unroll
    for (int d = 1; d < 32; d <<= 1) {
        int y = __shfl_up_sync(0xFFFFFFFFu, inc, d);
        if (lane >= d) inc += y;
    }

    // Block-level scan of warp totals (32 warps).
    __shared__ int warp_sums[32];
    if (lane == 31) warp_sums[wid] = inc;
    __syncthreads();
    if (wid == 0) {
        int s = warp_sums[lane];
#pragma unroll
        for (int d = 1; d < 32; d <<= 1) {
            int y = __shfl_up_sync(0xFFFFFFFFu, s, d);
            if (lane >= d) s += y;
        }
        warp_sums[lane] = s;   // inclusive over warps <= lane
    }
    __syncthreads();

    int off = (wid > 0 ? warp_sums[wid - 1] : 0) + (inc - c);

    // Ordered scatter of survivors; guard against >KEEP survivors (reference
    // truncates to keep_len).
#pragma unroll
    for (int i = 0; i < PER_T; ++i) {
        if (v[i] != FILLER) {
            if (off < KEEP) o[off] = v[i];
            ++off;
        }
    }
}

extern "C" void kernel_launch(void* const* d_in, const int* in_sizes, int n_in,
                              void* d_out, int out_size)
{
    // metadata order: x1 [B,C,4096] f32, x2 [B,C,4096] f32,
    //                 x3 [B,C,16384] f32, keep_len (int scalar)
    const float* x3 = (const float*)d_in[2];
    float* out = (float*)d_out;

    const int n_rows = in_sizes[2] / L_DIM;   // B*C = 2048

    compact_rows_kernel<<<n_rows, THREADS>>>(x3, out, n_rows);
}

// round 6
// speedup vs baseline: 2.1843x; 2.1843x over previous
#include <cuda_runtime.h>
#include <cstdint>

// Per-row stream compaction:
//   x3: [B*C, L] f32, L=16384. Drop entries exactly equal to 10.1f, keep
//   order, emit first KEEP=12288 survivors per row. Setup guarantees exactly
//   L-KEEP fillers per row, so output is fully written.
//
// R5 (= R4 resubmit after broker failure): smem staging — scattered STS into
// a 48 KB dynamic staging buffer, then coalesced float4 STG drain. The
// warp-sum scan array transiently reuses stage[0..31] (reads fenced by a
// __syncthreads before the scatter overwrites them), so total shared memory
// is exactly 49152 B dynamic + 0 B static: within the 48 KB default limit,
// no cudaFuncSetAttribute, kernel_launch is a bare kernel launch.

#define FILLER 10.1f

constexpr int L_DIM   = 16384;
constexpr int KEEP    = 12288;
constexpr int THREADS = 1024;
constexpr int PER_T   = L_DIM / THREADS;    // 16 elements per thread
constexpr int VEC     = PER_T / 4;          // 4 float4 loads per thread
constexpr int OUT_V4  = KEEP / 4 / THREADS; // 3 float4 stores per thread

__global__ __launch_bounds__(THREADS, 2)
void compact_rows_kernel(const float* __restrict__ x3,
                         float* __restrict__ out,
                         int n_rows)
{
    extern __shared__ float stage[];        // KEEP floats = 49152 B dynamic
    int* warp_sums = reinterpret_cast<int*>(stage);  // transient reuse

    const int row = blockIdx.x;
    if (row >= n_rows) return;

    const float* __restrict__ in = x3 + (size_t)row * L_DIM;
    float* __restrict__ o        = out + (size_t)row * KEEP;

    const int tid  = threadIdx.x;
    const int lane = tid & 31;
    const int wid  = tid >> 5;

    // Each thread owns a contiguous run of 16 elements (order preservation).
    float v[PER_T];
    const float4* __restrict__ in4 =
        reinterpret_cast<const float4*>(in + tid * PER_T);
#pragma unroll
    for (int j = 0; j < VEC; ++j) {
        float4 t = in4[j];
        v[4 * j + 0] = t.x;
        v[4 * j + 1] = t.y;
        v[4 * j + 2] = t.z;
        v[4 * j + 3] = t.w;
    }

    // Survivor count for this thread.
    int c = 0;
#pragma unroll
    for (int i = 0; i < PER_T; ++i) c += (v[i] != FILLER) ? 1 : 0;

    // Warp-level inclusive scan of counts.
    int inc = c;
#pragma unroll
    for (int d = 1; d < 32; d <<= 1) {
        int y = __shfl_up_sync(0xFFFFFFFFu, inc, d);
        if (lane >= d) inc += y;
    }

    // Block-level scan of warp totals (32 warps) held in stage[0..31].
    if (lane == 31) warp_sums[wid] = inc;
    __syncthreads();
    if (wid == 0) {
        int s = warp_sums[lane];
#pragma unroll
        for (int d = 1; d < 32; d <<= 1) {
            int y = __shfl_up_sync(0xFFFFFFFFu, s, d);
            if (lane >= d) s += y;
        }
        warp_sums[lane] = s;   // inclusive over warps <= lane
    }
    __syncthreads();

    const int off0 = (wid > 0 ? warp_sums[wid - 1] : 0) + (inc - c);

    // All reads of warp_sums must retire before the scatter overwrites
    // stage[0..31].
    __syncthreads();

    // Ordered scatter of survivors into the shared staging buffer.
    int off = off0;
#pragma unroll
    for (int i = 0; i < PER_T; ++i) {
        if (v[i] != FILLER) {
            if (off < KEEP) stage[off] = v[i];
            ++off;
        }
    }
    __syncthreads();

    // Coalesced float4 drain: smem -> global.
    float4* __restrict__ o4 = reinterpret_cast<float4*>(o);
    const float4* __restrict__ s4 = reinterpret_cast<const float4*>(stage);
#pragma unroll
    for (int k = 0; k < OUT_V4; ++k) {
        o4[tid + k * THREADS] = s4[tid + k * THREADS];
    }
}

extern "C" void kernel_launch(void* const* d_in, const int* in_sizes, int n_in,
                              void* d_out, int out_size)
{
    // metadata order: x1 [B,C,4096] f32, x2 [B,C,4096] f32,
    //                 x3 [B,C,16384] f32, keep_len (int scalar)
    const float* x3 = (const float*)d_in[2];
    float* out = (float*)d_out;

    const int n_rows = in_sizes[2] / L_DIM;            // B*C = 2048
    const int smem_bytes = KEEP * (int)sizeof(float);  // 49152 B = 48 KB

    compact_rows_kernel<<<n_rows, THREADS, smem_bytes>>>(x3, out, n_rows);
}